// round 1
// baseline (speedup 1.0000x reference)
#include <cuda_runtime.h>
#include <cuda_bf16.h>
#include <cstddef>

// Problem-fixed dimensions (shape-specialized per dataset entry).
#define D_IN   128
#define D_OUT  128
#define D_EDGE 32
#define MAX_NODES 100000

// Scratch: per-node precomputed (X_src @ W_src + b) for each relation.
__device__ float g_xwu[(size_t)MAX_NODES * D_OUT];  // users  (feeds relation ui)
__device__ float g_xwi[(size_t)MAX_NODES * D_OUT];  // items  (feeds relation iu)

// ---------------------------------------------------------------------------
// Vector float4 reduction to global memory (sm_90+): one REDG per 16 bytes.
// ---------------------------------------------------------------------------
__device__ __forceinline__ void red_add_v4(float* p, float4 v) {
    asm volatile("red.global.add.v4.f32 [%0], {%1,%2,%3,%4};"
                 :: "l"(p), "f"(v.x), "f"(v.y), "f"(v.z), "f"(v.w)
                 : "memory");
}

// ---------------------------------------------------------------------------
// Node transform: for a tile of 128 rows, compute BOTH
//   Y1 = X @ W1 + b1   (scratch XW for the relation gather)
//   Y2 = X @ W2 + b2   (self-loop, written to d_out -> also initializes it)
// Block = 512 threads (16 warps), 8 rows per warp, 4 cols per lane.
// Dynamic smem: W1 (64KB) + W2 (64KB) + biases (1KB) + X tile (64KB).
// ---------------------------------------------------------------------------
#define NODE_THREADS 512
#define NODE_ROWS    128
#define NODE_SMEM_FLOATS (16384 + 16384 + 256 + 16384)
#define NODE_SMEM_BYTES  (NODE_SMEM_FLOATS * 4)

__global__ __launch_bounds__(NODE_THREADS, 1)
void node_kernel(const float* __restrict__ X,
                 const float* __restrict__ W1, const float* __restrict__ b1,
                 float* __restrict__ Y1,
                 const float* __restrict__ W2, const float* __restrict__ b2,
                 float* __restrict__ Y2,
                 int n)
{
    extern __shared__ float sm[];
    float* W1s = sm;               // 128*128
    float* W2s = sm + 16384;       // 128*128
    float* bs  = sm + 32768;       // 128 + 128
    float* Xs  = sm + 33024;       // 128 rows * 128

    const int tid = threadIdx.x;

    // Stage weights (float4 copies).
    {
        const float4* W1g = (const float4*)W1;
        const float4* W2g = (const float4*)W2;
        float4* W1sv = (float4*)W1s;
        float4* W2sv = (float4*)W2s;
        #pragma unroll
        for (int i = tid; i < 4096; i += NODE_THREADS) W1sv[i] = W1g[i];
        #pragma unroll
        for (int i = tid; i < 4096; i += NODE_THREADS) W2sv[i] = W2g[i];
        if (tid < 128) { bs[tid] = b1[tid]; bs[128 + tid] = b2[tid]; }
    }

    const int row_base = blockIdx.x * NODE_ROWS;

    // Stage X tile (zeros for out-of-range rows).
    {
        const float4* Xg = (const float4*)X;
        float4* Xsv = (float4*)Xs;
        #pragma unroll
        for (int i = tid; i < 4096; i += NODE_THREADS) {
            int r = row_base + (i >> 5);
            Xsv[i] = (r < n) ? Xg[(size_t)r * 32 + (i & 31)]
                             : make_float4(0.f, 0.f, 0.f, 0.f);
        }
    }
    __syncthreads();

    const int warp = tid >> 5;
    const int lane = tid & 31;
    const int r0 = warp * 8;

    float4 bias1 = ((const float4*)bs)[lane];
    float4 bias2 = ((const float4*)(bs + 128))[lane];

    float4 a1[8], a2[8];
    #pragma unroll
    for (int r = 0; r < 8; r++) { a1[r] = bias1; a2[r] = bias2; }

    const float4* W1v = (const float4*)W1s;
    const float4* W2v = (const float4*)W2s;

    #pragma unroll 4
    for (int k = 0; k < 128; k++) {
        float4 w1 = W1v[k * 32 + lane];
        float4 w2 = W2v[k * 32 + lane];
        #pragma unroll
        for (int r = 0; r < 8; r++) {
            float xv = Xs[(r0 + r) * 128 + k];   // broadcast LDS
            a1[r].x += xv * w1.x; a1[r].y += xv * w1.y;
            a1[r].z += xv * w1.z; a1[r].w += xv * w1.w;
            a2[r].x += xv * w2.x; a2[r].y += xv * w2.y;
            a2[r].z += xv * w2.z; a2[r].w += xv * w2.w;
        }
    }

    #pragma unroll
    for (int r = 0; r < 8; r++) {
        int row = row_base + r0 + r;
        if (row < n) {
            ((float4*)(Y1 + (size_t)row * 128))[lane] = a1[r];
            ((float4*)(Y2 + (size_t)row * 128))[lane] = a2[r];
        }
    }
}

// ---------------------------------------------------------------------------
// Relation kernel: warp per edge (grid-stride).
//   msg = relu( XW[src] + Xe[e] @ W_edge )   (bias already folded into XW)
//   out[dst] += msg   (red.global.add.v4.f32)
// W_edge (32x128 = 16KB) in static smem. D_EDGE == 32 == warp size: each lane
// holds one edge feature, broadcast via shfl.
// ---------------------------------------------------------------------------
#define REL_THREADS 256

__global__ __launch_bounds__(REL_THREADS)
void rel_kernel(const float* __restrict__ XW,
                const float* __restrict__ Xe,
                const int* __restrict__ src,
                const int* __restrict__ dst,
                const float* __restrict__ We,
                float* __restrict__ out,
                int E)
{
    __shared__ float Wes[D_EDGE * D_OUT];   // 16 KB
    const int tid = threadIdx.x;
    {
        const float4* Weg = (const float4*)We;
        float4* Wesv = (float4*)Wes;
        #pragma unroll
        for (int i = tid; i < (D_EDGE * D_OUT) / 4; i += REL_THREADS)
            Wesv[i] = Weg[i];
    }
    __syncthreads();

    const int lane = tid & 31;
    const int gwarp = (blockIdx.x * REL_THREADS + tid) >> 5;
    const int nwarp = (gridDim.x * REL_THREADS) >> 5;
    const float4* Wev = (const float4*)Wes;

    for (int e = gwarp; e < E; e += nwarp) {
        const int s = __ldg(&src[e]);
        const int d = __ldg(&dst[e]);
        const float ev = __ldg(&Xe[(size_t)e * D_EDGE + lane]);

        float4 acc = __ldg((const float4*)(XW + (size_t)s * 128) + lane);

        #pragma unroll
        for (int k = 0; k < 32; k++) {
            float xk = __shfl_sync(0xffffffffu, ev, k);
            float4 w = Wev[k * 32 + lane];
            acc.x += xk * w.x; acc.y += xk * w.y;
            acc.z += xk * w.z; acc.w += xk * w.w;
        }

        acc.x = fmaxf(acc.x, 0.f);
        acc.y = fmaxf(acc.y, 0.f);
        acc.z = fmaxf(acc.z, 0.f);
        acc.w = fmaxf(acc.w, 0.f);

        red_add_v4(out + (size_t)d * 128 + 4 * lane, acc);
    }
}

// ---------------------------------------------------------------------------
// kernel_launch
// metadata order:
//  0 X_user  1 X_item  2 Xe_ui  3 Xe_iu
//  4 W_src_ui  5 W_edge_ui  6 b_ui
//  7 W_src_iu  8 W_edge_iu  9 b_iu
// 10 Wl_user 11 bl_user 12 Wl_item 13 bl_item
// 14 src_ui 15 dst_ui 16 src_iu 17 dst_iu
// Output: [H_user (n_user*128) | H_item (n_item*128)] float32
// ---------------------------------------------------------------------------
extern "C" void kernel_launch(void* const* d_in, const int* in_sizes, int n_in,
                              void* d_out, int out_size)
{
    const float* X_user   = (const float*)d_in[0];
    const float* X_item   = (const float*)d_in[1];
    const float* Xe_ui    = (const float*)d_in[2];
    const float* Xe_iu    = (const float*)d_in[3];
    const float* W_src_ui = (const float*)d_in[4];
    const float* W_edge_ui= (const float*)d_in[5];
    const float* b_ui     = (const float*)d_in[6];
    const float* W_src_iu = (const float*)d_in[7];
    const float* W_edge_iu= (const float*)d_in[8];
    const float* b_iu     = (const float*)d_in[9];
    const float* Wl_user  = (const float*)d_in[10];
    const float* bl_user  = (const float*)d_in[11];
    const float* Wl_item  = (const float*)d_in[12];
    const float* bl_item  = (const float*)d_in[13];
    const int*   src_ui   = (const int*)d_in[14];
    const int*   dst_ui   = (const int*)d_in[15];
    const int*   src_iu   = (const int*)d_in[16];
    const int*   dst_iu   = (const int*)d_in[17];

    const int n_user = in_sizes[0] / D_IN;
    const int n_item = in_sizes[1] / D_IN;
    const int E      = in_sizes[14];

    float* H_user = (float*)d_out;
    float* H_item = (float*)d_out + (size_t)n_user * D_OUT;

    void* p_xwu = nullptr; void* p_xwi = nullptr;
    cudaGetSymbolAddress(&p_xwu, g_xwu);
    cudaGetSymbolAddress(&p_xwi, g_xwi);
    float* xwu = (float*)p_xwu;
    float* xwi = (float*)p_xwi;

    cudaFuncSetAttribute(node_kernel,
                         cudaFuncAttributeMaxDynamicSharedMemorySize,
                         NODE_SMEM_BYTES);

    // 1) user nodes: XWu = X_user @ W_src_ui + b_ui ; H_user = X_user @ Wl_user + bl_user
    node_kernel<<<(n_user + NODE_ROWS - 1) / NODE_ROWS, NODE_THREADS, NODE_SMEM_BYTES>>>(
        X_user, W_src_ui, b_ui, xwu, Wl_user, bl_user, H_user, n_user);

    // 2) item nodes: XWi = X_item @ W_src_iu + b_iu ; H_item = X_item @ Wl_item + bl_item
    node_kernel<<<(n_item + NODE_ROWS - 1) / NODE_ROWS, NODE_THREADS, NODE_SMEM_BYTES>>>(
        X_item, W_src_iu, b_iu, xwi, Wl_item, bl_item, H_item, n_item);

    // 3) relation ui: users -> items (adds into H_item)
    rel_kernel<<<1480, REL_THREADS>>>(xwu, Xe_ui, src_ui, dst_ui, W_edge_ui, H_item, E);

    // 4) relation iu: items -> users (adds into H_user)
    rel_kernel<<<1480, REL_THREADS>>>(xwi, Xe_iu, src_iu, dst_iu, W_edge_iu, H_user, E);
}

// round 2
// speedup vs baseline: 1.3744x; 1.3744x over previous
#include <cuda_runtime.h>
#include <cuda_bf16.h>
#include <cstddef>

#define D_IN   128
#define D_OUT  128
#define D_EDGE 32
#define MAX_NODES 100000

// Scratch: per-node precomputed (X_src @ W_src + b) for each relation.
__device__ float g_xwu[(size_t)MAX_NODES * D_OUT];
__device__ float g_xwi[(size_t)MAX_NODES * D_OUT];

// ---------------------------------------------------------------------------
// Packed f32x2 helpers (sm_10x: fma.rn.f32x2 only reachable via PTX).
// ---------------------------------------------------------------------------
__device__ __forceinline__ unsigned long long pk2(float x) {
    unsigned long long r;
    asm("mov.b64 %0, {%1, %1};" : "=l"(r) : "f"(x));
    return r;
}
__device__ __forceinline__ unsigned long long fma2(unsigned long long a,
                                                   unsigned long long b,
                                                   unsigned long long c) {
    unsigned long long d;
    asm("fma.rn.f32x2 %0, %1, %2, %3;" : "=l"(d) : "l"(a), "l"(b), "l"(c));
    return d;
}

union F4U2 { float4 f; ulonglong2 u; };

__device__ __forceinline__ void red_add_v4(float* p, float4 v) {
    asm volatile("red.global.add.v4.f32 [%0], {%1,%2,%3,%4};"
                 :: "l"(p), "f"(v.x), "f"(v.y), "f"(v.z), "f"(v.w)
                 : "memory");
}

// ---------------------------------------------------------------------------
// Node transform: per 128-row tile compute BOTH
//   Y1 = X @ W1 + b1   (scratch XW for the relation gather)
//   Y2 = X @ W2 + b2   (self-loop -> d_out, also initializes it)
// 512 threads / 16 warps, 8 rows per warp, 4 cols per lane; f32x2 FMA.
// ---------------------------------------------------------------------------
#define NODE_THREADS 512
#define NODE_ROWS    128
#define NODE_SMEM_FLOATS (16384 + 16384 + 256 + 16384)
#define NODE_SMEM_BYTES  (NODE_SMEM_FLOATS * 4)

__global__ __launch_bounds__(NODE_THREADS, 1)
void node_kernel(const float* __restrict__ X,
                 const float* __restrict__ W1, const float* __restrict__ b1,
                 float* __restrict__ Y1,
                 const float* __restrict__ W2, const float* __restrict__ b2,
                 float* __restrict__ Y2,
                 int n)
{
    extern __shared__ float sm[];
    float* W1s = sm;               // 128*128
    float* W2s = sm + 16384;       // 128*128
    float* bs  = sm + 32768;       // 128 + 128
    float* Xs  = sm + 33024;       // 128 rows * 128

    const int tid = threadIdx.x;

    {
        const float4* W1g = (const float4*)W1;
        const float4* W2g = (const float4*)W2;
        float4* W1sv = (float4*)W1s;
        float4* W2sv = (float4*)W2s;
        #pragma unroll
        for (int i = tid; i < 4096; i += NODE_THREADS) W1sv[i] = W1g[i];
        #pragma unroll
        for (int i = tid; i < 4096; i += NODE_THREADS) W2sv[i] = W2g[i];
        if (tid < 128) { bs[tid] = b1[tid]; bs[128 + tid] = b2[tid]; }
    }

    const int row_base = blockIdx.x * NODE_ROWS;
    {
        const float4* Xg = (const float4*)X;
        float4* Xsv = (float4*)Xs;
        #pragma unroll
        for (int i = tid; i < 4096; i += NODE_THREADS) {
            int r = row_base + (i >> 5);
            Xsv[i] = (r < n) ? Xg[(size_t)r * 32 + (i & 31)]
                             : make_float4(0.f, 0.f, 0.f, 0.f);
        }
    }
    __syncthreads();

    const int warp = tid >> 5;
    const int lane = tid & 31;
    const int r0 = warp * 8;

    F4U2 bias1, bias2;
    bias1.f = ((const float4*)bs)[lane];
    bias2.f = ((const float4*)(bs + 128))[lane];

    ulonglong2 a1[8], a2[8];
    #pragma unroll
    for (int r = 0; r < 8; r++) { a1[r] = bias1.u; a2[r] = bias2.u; }

    const ulonglong2* W1v = (const ulonglong2*)W1s;  // [k*32 + lane] = 4 cols
    const ulonglong2* W2v = (const ulonglong2*)W2s;

    #pragma unroll 2
    for (int k2 = 0; k2 < 64; k2++) {
        const int k0 = 2 * k2;
        ulonglong2 w1a = W1v[k0 * 32 + lane];
        ulonglong2 w1b = W1v[(k0 + 1) * 32 + lane];
        ulonglong2 w2a = W2v[k0 * 32 + lane];
        ulonglong2 w2b = W2v[(k0 + 1) * 32 + lane];
        #pragma unroll
        for (int r = 0; r < 8; r++) {
            float2 xv = *(const float2*)&Xs[(r0 + r) * 128 + k0];  // LDS.64 bcast
            unsigned long long xa = pk2(xv.x);
            unsigned long long xb = pk2(xv.y);
            a1[r].x = fma2(xa, w1a.x, a1[r].x);
            a1[r].y = fma2(xa, w1a.y, a1[r].y);
            a2[r].x = fma2(xa, w2a.x, a2[r].x);
            a2[r].y = fma2(xa, w2a.y, a2[r].y);
            a1[r].x = fma2(xb, w1b.x, a1[r].x);
            a1[r].y = fma2(xb, w1b.y, a1[r].y);
            a2[r].x = fma2(xb, w2b.x, a2[r].x);
            a2[r].y = fma2(xb, w2b.y, a2[r].y);
        }
    }

    #pragma unroll
    for (int r = 0; r < 8; r++) {
        int row = row_base + r0 + r;
        if (row < n) {
            F4U2 o1, o2; o1.u = a1[r]; o2.u = a2[r];
            ((float4*)(Y1 + (size_t)row * 128))[lane] = o1.f;
            ((float4*)(Y2 + (size_t)row * 128))[lane] = o2.f;
        }
    }
}

// ---------------------------------------------------------------------------
// Relation kernel v2:
//   * warp processes 4 edges per group (grid-stride)
//   * W_edge column slice (32 x 4 floats) held in REGISTERS (loop-invariant)
//   * f32x2 packed FMA, shfl-broadcast edge features
//   * red.global.add.v4.f32 scatter
// ---------------------------------------------------------------------------
#define REL_THREADS 256
#define EPW 4

__global__ __launch_bounds__(REL_THREADS)
void rel_kernel(const float* __restrict__ XW,
                const float* __restrict__ Xe,
                const int* __restrict__ src,
                const int* __restrict__ dst,
                const float* __restrict__ We,
                float* __restrict__ out,
                int E)
{
    const int lane  = threadIdx.x & 31;
    const int gwarp = (blockIdx.x * REL_THREADS + threadIdx.x) >> 5;
    const int nwarp = (gridDim.x * REL_THREADS) >> 5;

    // Preload this lane's W_edge column slice: Wr[k] = We[k][4*lane..4*lane+3]
    ulonglong2 Wr[32];
    #pragma unroll
    for (int k = 0; k < 32; k++) {
        F4U2 w; w.f = __ldg((const float4*)(We + k * D_OUT) + lane);
        Wr[k] = w.u;
    }

    for (int base = gwarp * EPW; base < E; base += nwarp * EPW) {
        if (base + EPW <= E) {
            int4 ss = __ldg((const int4*)(src + base));
            int4 dd = __ldg((const int4*)(dst + base));

            float ev0 = __ldg(Xe + (size_t)(base + 0) * D_EDGE + lane);
            float ev1 = __ldg(Xe + (size_t)(base + 1) * D_EDGE + lane);
            float ev2 = __ldg(Xe + (size_t)(base + 2) * D_EDGE + lane);
            float ev3 = __ldg(Xe + (size_t)(base + 3) * D_EDGE + lane);

            F4U2 g0, g1, g2, g3;
            g0.f = __ldg((const float4*)(XW + (size_t)ss.x * 128) + lane);
            g1.f = __ldg((const float4*)(XW + (size_t)ss.y * 128) + lane);
            g2.f = __ldg((const float4*)(XW + (size_t)ss.z * 128) + lane);
            g3.f = __ldg((const float4*)(XW + (size_t)ss.w * 128) + lane);
            ulonglong2 a0 = g0.u, a1 = g1.u, a2 = g2.u, a3 = g3.u;

            #pragma unroll
            for (int k = 0; k < 32; k++) {
                unsigned long long x0 = pk2(__shfl_sync(0xffffffffu, ev0, k));
                a0.x = fma2(x0, Wr[k].x, a0.x);
                a0.y = fma2(x0, Wr[k].y, a0.y);
                unsigned long long x1 = pk2(__shfl_sync(0xffffffffu, ev1, k));
                a1.x = fma2(x1, Wr[k].x, a1.x);
                a1.y = fma2(x1, Wr[k].y, a1.y);
                unsigned long long x2 = pk2(__shfl_sync(0xffffffffu, ev2, k));
                a2.x = fma2(x2, Wr[k].x, a2.x);
                a2.y = fma2(x2, Wr[k].y, a2.y);
                unsigned long long x3 = pk2(__shfl_sync(0xffffffffu, ev3, k));
                a3.x = fma2(x3, Wr[k].x, a3.x);
                a3.y = fma2(x3, Wr[k].y, a3.y);
            }

            F4U2 o0, o1, o2, o3;
            o0.u = a0; o1.u = a1; o2.u = a2; o3.u = a3;
            float4 r0 = o0.f, r1 = o1.f, r2 = o2.f, r3 = o3.f;
            r0.x = fmaxf(r0.x, 0.f); r0.y = fmaxf(r0.y, 0.f);
            r0.z = fmaxf(r0.z, 0.f); r0.w = fmaxf(r0.w, 0.f);
            r1.x = fmaxf(r1.x, 0.f); r1.y = fmaxf(r1.y, 0.f);
            r1.z = fmaxf(r1.z, 0.f); r1.w = fmaxf(r1.w, 0.f);
            r2.x = fmaxf(r2.x, 0.f); r2.y = fmaxf(r2.y, 0.f);
            r2.z = fmaxf(r2.z, 0.f); r2.w = fmaxf(r2.w, 0.f);
            r3.x = fmaxf(r3.x, 0.f); r3.y = fmaxf(r3.y, 0.f);
            r3.z = fmaxf(r3.z, 0.f); r3.w = fmaxf(r3.w, 0.f);

            red_add_v4(out + (size_t)dd.x * 128 + 4 * lane, r0);
            red_add_v4(out + (size_t)dd.y * 128 + 4 * lane, r1);
            red_add_v4(out + (size_t)dd.z * 128 + 4 * lane, r2);
            red_add_v4(out + (size_t)dd.w * 128 + 4 * lane, r3);
        } else {
            for (int e = base; e < E; e++) {
                int s = __ldg(&src[e]);
                int d = __ldg(&dst[e]);
                float ev = __ldg(Xe + (size_t)e * D_EDGE + lane);
                F4U2 g; g.f = __ldg((const float4*)(XW + (size_t)s * 128) + lane);
                ulonglong2 a = g.u;
                #pragma unroll
                for (int k = 0; k < 32; k++) {
                    unsigned long long x = pk2(__shfl_sync(0xffffffffu, ev, k));
                    a.x = fma2(x, Wr[k].x, a.x);
                    a.y = fma2(x, Wr[k].y, a.y);
                }
                F4U2 o; o.u = a;
                float4 r = o.f;
                r.x = fmaxf(r.x, 0.f); r.y = fmaxf(r.y, 0.f);
                r.z = fmaxf(r.z, 0.f); r.w = fmaxf(r.w, 0.f);
                red_add_v4(out + (size_t)d * 128 + 4 * lane, r);
            }
        }
    }
}

// ---------------------------------------------------------------------------
// kernel_launch (metadata order unchanged)
// ---------------------------------------------------------------------------
extern "C" void kernel_launch(void* const* d_in, const int* in_sizes, int n_in,
                              void* d_out, int out_size)
{
    const float* X_user   = (const float*)d_in[0];
    const float* X_item   = (const float*)d_in[1];
    const float* Xe_ui    = (const float*)d_in[2];
    const float* Xe_iu    = (const float*)d_in[3];
    const float* W_src_ui = (const float*)d_in[4];
    const float* W_edge_ui= (const float*)d_in[5];
    const float* b_ui     = (const float*)d_in[6];
    const float* W_src_iu = (const float*)d_in[7];
    const float* W_edge_iu= (const float*)d_in[8];
    const float* b_iu     = (const float*)d_in[9];
    const float* Wl_user  = (const float*)d_in[10];
    const float* bl_user  = (const float*)d_in[11];
    const float* Wl_item  = (const float*)d_in[12];
    const float* bl_item  = (const float*)d_in[13];
    const int*   src_ui   = (const int*)d_in[14];
    const int*   dst_ui   = (const int*)d_in[15];
    const int*   src_iu   = (const int*)d_in[16];
    const int*   dst_iu   = (const int*)d_in[17];

    const int n_user = in_sizes[0] / D_IN;
    const int n_item = in_sizes[1] / D_IN;
    const int E      = in_sizes[14];

    float* H_user = (float*)d_out;
    float* H_item = (float*)d_out + (size_t)n_user * D_OUT;

    void* p_xwu = nullptr; void* p_xwi = nullptr;
    cudaGetSymbolAddress(&p_xwu, g_xwu);
    cudaGetSymbolAddress(&p_xwi, g_xwi);
    float* xwu = (float*)p_xwu;
    float* xwi = (float*)p_xwi;

    cudaFuncSetAttribute(node_kernel,
                         cudaFuncAttributeMaxDynamicSharedMemorySize,
                         NODE_SMEM_BYTES);

    node_kernel<<<(n_user + NODE_ROWS - 1) / NODE_ROWS, NODE_THREADS, NODE_SMEM_BYTES>>>(
        X_user, W_src_ui, b_ui, xwu, Wl_user, bl_user, H_user, n_user);

    node_kernel<<<(n_item + NODE_ROWS - 1) / NODE_ROWS, NODE_THREADS, NODE_SMEM_BYTES>>>(
        X_item, W_src_iu, b_iu, xwi, Wl_item, bl_item, H_item, n_item);

    rel_kernel<<<1480, REL_THREADS>>>(xwu, Xe_ui, src_ui, dst_ui, W_edge_ui, H_item, E);
    rel_kernel<<<1480, REL_THREADS>>>(xwi, Xe_iu, src_iu, dst_iu, W_edge_iu, H_user, E);
}

// round 3
// speedup vs baseline: 1.8692x; 1.3601x over previous
#include <cuda_runtime.h>
#include <cuda_bf16.h>
#include <cstddef>

#define D_IN   128
#define D_OUT  128
#define D_EDGE 32
#define MAX_NODES 100000

// Scratch: per-node precomputed (X_src @ W_src + b) for each relation.
__device__ float g_xwu[(size_t)MAX_NODES * D_OUT];
__device__ float g_xwi[(size_t)MAX_NODES * D_OUT];

// ---------------------------------------------------------------------------
// Packed f32x2 helpers (sm_10x: fma.rn.f32x2 only reachable via PTX).
// ---------------------------------------------------------------------------
__device__ __forceinline__ unsigned long long pk2(float x) {
    unsigned long long r;
    asm("mov.b64 %0, {%1, %1};" : "=l"(r) : "f"(x));
    return r;
}
__device__ __forceinline__ unsigned long long fma2(unsigned long long a,
                                                   unsigned long long b,
                                                   unsigned long long c) {
    unsigned long long d;
    asm("fma.rn.f32x2 %0, %1, %2, %3;" : "=l"(d) : "l"(a), "l"(b), "l"(c));
    return d;
}

union F4U2 { float4 f; ulonglong2 u; };

__device__ __forceinline__ void red_add_v4(float* p, float4 v) {
    asm volatile("red.global.add.v4.f32 [%0], {%1,%2,%3,%4};"
                 :: "l"(p), "f"(v.x), "f"(v.y), "f"(v.z), "f"(v.w)
                 : "memory");
}

// ---------------------------------------------------------------------------
// Node transform v2: one GEMM per block (blockIdx.y picks W1/b1/Y1 or W2/b2/Y2)
// so smem/block is ~97KB -> 2 resident blocks/SM overlap staging & compute.
//   Y = X @ W + b     (64-row tiles, 512 threads, 4 rows/warp, 4 cols/lane)
// ---------------------------------------------------------------------------
#define NODE_THREADS 512
#define NODE_ROWS    64
#define NODE_SMEM_FLOATS (16384 + 128 + NODE_ROWS * 128)
#define NODE_SMEM_BYTES  (NODE_SMEM_FLOATS * 4)

__global__ __launch_bounds__(NODE_THREADS, 2)
void node_kernel(const float* __restrict__ X,
                 const float* __restrict__ W1, const float* __restrict__ b1,
                 float* __restrict__ Y1,
                 const float* __restrict__ W2, const float* __restrict__ b2,
                 float* __restrict__ Y2,
                 int n)
{
    extern __shared__ float sm[];
    float* Ws = sm;                  // 128*128
    float* bs = sm + 16384;          // 128
    float* Xs = sm + 16512;          // 64 rows * 128

    const float* W = blockIdx.y ? W2 : W1;
    const float* b = blockIdx.y ? b2 : b1;
    float*       Y = blockIdx.y ? Y2 : Y1;

    const int tid = threadIdx.x;

    // Stage weights + bias.
    {
        const float4* Wg = (const float4*)W;
        float4* Wsv = (float4*)Ws;
        #pragma unroll
        for (int i = tid; i < 4096; i += NODE_THREADS) Wsv[i] = Wg[i];
        if (tid < 128) bs[tid] = b[tid];
    }

    const int row_base = blockIdx.x * NODE_ROWS;
    {
        const float4* Xg = (const float4*)X;
        float4* Xsv = (float4*)Xs;
        #pragma unroll
        for (int i = tid; i < NODE_ROWS * 32; i += NODE_THREADS) {
            int r = row_base + (i >> 5);
            Xsv[i] = (r < n) ? Xg[(size_t)r * 32 + (i & 31)]
                             : make_float4(0.f, 0.f, 0.f, 0.f);
        }
    }
    __syncthreads();

    const int warp = tid >> 5;
    const int lane = tid & 31;
    const int r0 = warp * 4;          // 16 warps * 4 rows = 64

    F4U2 bias; bias.f = ((const float4*)bs)[lane];

    ulonglong2 acc[4];
    #pragma unroll
    for (int r = 0; r < 4; r++) acc[r] = bias.u;

    const ulonglong2* Wv = (const ulonglong2*)Ws;   // [k*32 + lane] = 4 cols

    #pragma unroll 4
    for (int k2 = 0; k2 < 64; k2++) {
        const int k0 = 2 * k2;
        ulonglong2 wa = Wv[k0 * 32 + lane];
        ulonglong2 wb = Wv[(k0 + 1) * 32 + lane];
        #pragma unroll
        for (int r = 0; r < 4; r++) {
            float2 xv = *(const float2*)&Xs[(r0 + r) * 128 + k0]; // LDS.64 bcast
            unsigned long long xa = pk2(xv.x);
            unsigned long long xb = pk2(xv.y);
            acc[r].x = fma2(xa, wa.x, acc[r].x);
            acc[r].y = fma2(xa, wa.y, acc[r].y);
            acc[r].x = fma2(xb, wb.x, acc[r].x);
            acc[r].y = fma2(xb, wb.y, acc[r].y);
        }
    }

    #pragma unroll
    for (int r = 0; r < 4; r++) {
        int row = row_base + r0 + r;
        if (row < n) {
            F4U2 o; o.u = acc[r];
            ((float4*)(Y + (size_t)row * 128))[lane] = o.f;
        }
    }
}

// ---------------------------------------------------------------------------
// Relation kernel v3: tiled smem GEMM (no shfl, no register-resident W).
//   * W_edge (32x128, 16KB) staged ONCE per persistent block
//   * 64-edge Xe tiles (8KB) + indices staged cooperatively, grid-stride
//   * warp: 8 edges x (4 cols/lane), LDS-broadcast Xe, LDS.128 W
//   * acc seeded by XW[src] gather (bias folded), relu, red.v4 scatter
// ---------------------------------------------------------------------------
#define REL_THREADS 256
#define REL_TILE 64

__global__ __launch_bounds__(REL_THREADS, 3)
void rel_kernel(const float* __restrict__ XW,
                const float* __restrict__ Xe,
                const int* __restrict__ src,
                const int* __restrict__ dst,
                const float* __restrict__ We,
                float* __restrict__ out,
                int E)
{
    __shared__ float Wes[D_EDGE * D_OUT];       // 16 KB
    __shared__ float Xs[REL_TILE * D_EDGE];     // 8 KB
    __shared__ int   Ss[REL_TILE];
    __shared__ int   Ds[REL_TILE];

    const int tid = threadIdx.x;

    {
        const float4* Weg = (const float4*)We;
        float4* Wesv = (float4*)Wes;
        #pragma unroll
        for (int i = tid; i < (D_EDGE * D_OUT) / 4; i += REL_THREADS)
            Wesv[i] = Weg[i];
    }

    const int warp = tid >> 5;
    const int lane = tid & 31;
    const int r0 = warp * 8;                    // 8 warps * 8 edges = 64
    const ulonglong2* Wv = (const ulonglong2*)Wes;

    const int ntiles = (E + REL_TILE - 1) / REL_TILE;

    for (int t = blockIdx.x; t < ntiles; t += gridDim.x) {
        const int e0 = t * REL_TILE;
        __syncthreads();   // smem reuse vs previous tile readers

        // Stage Xe tile (8 float4 per edge), zero-pad past E.
        {
            const float4* Xeg = (const float4*)(Xe + (size_t)e0 * D_EDGE);
            const int lim = (E - e0) * (D_EDGE / 4);
            float4* Xsv = (float4*)Xs;
            #pragma unroll
            for (int i = tid; i < REL_TILE * (D_EDGE / 4); i += REL_THREADS)
                Xsv[i] = (i < lim) ? Xeg[i] : make_float4(0.f, 0.f, 0.f, 0.f);
        }
        if (tid < REL_TILE) {
            int e = e0 + tid;
            Ss[tid] = (e < E) ? __ldg(&src[e]) : 0;
            Ds[tid] = (e < E) ? __ldg(&dst[e]) : 0;
        }
        __syncthreads();

        // Seed accumulators with gathered XW rows (MLP=8 per warp).
        ulonglong2 acc[8];
        #pragma unroll
        for (int r = 0; r < 8; r++) {
            int s = Ss[r0 + r];
            F4U2 g; g.f = __ldg((const float4*)(XW + (size_t)s * 128) + lane);
            acc[r] = g.u;
        }

        #pragma unroll 4
        for (int k2 = 0; k2 < D_EDGE / 2; k2++) {
            const int k0 = 2 * k2;
            ulonglong2 wa = Wv[k0 * 32 + lane];
            ulonglong2 wb = Wv[(k0 + 1) * 32 + lane];
            #pragma unroll
            for (int r = 0; r < 8; r++) {
                float2 xv = *(const float2*)&Xs[(r0 + r) * D_EDGE + k0];
                unsigned long long xa = pk2(xv.x);
                unsigned long long xb = pk2(xv.y);
                acc[r].x = fma2(xa, wa.x, acc[r].x);
                acc[r].y = fma2(xa, wa.y, acc[r].y);
                acc[r].x = fma2(xb, wb.x, acc[r].x);
                acc[r].y = fma2(xb, wb.y, acc[r].y);
            }
        }

        #pragma unroll
        for (int r = 0; r < 8; r++) {
            if (e0 + r0 + r < E) {
                F4U2 o; o.u = acc[r];
                float4 v = o.f;
                v.x = fmaxf(v.x, 0.f); v.y = fmaxf(v.y, 0.f);
                v.z = fmaxf(v.z, 0.f); v.w = fmaxf(v.w, 0.f);
                red_add_v4(out + (size_t)Ds[r0 + r] * 128 + 4 * lane, v);
            }
        }
    }
}

// ---------------------------------------------------------------------------
// kernel_launch (metadata order unchanged)
// ---------------------------------------------------------------------------
extern "C" void kernel_launch(void* const* d_in, const int* in_sizes, int n_in,
                              void* d_out, int out_size)
{
    const float* X_user   = (const float*)d_in[0];
    const float* X_item   = (const float*)d_in[1];
    const float* Xe_ui    = (const float*)d_in[2];
    const float* Xe_iu    = (const float*)d_in[3];
    const float* W_src_ui = (const float*)d_in[4];
    const float* W_edge_ui= (const float*)d_in[5];
    const float* b_ui     = (const float*)d_in[6];
    const float* W_src_iu = (const float*)d_in[7];
    const float* W_edge_iu= (const float*)d_in[8];
    const float* b_iu     = (const float*)d_in[9];
    const float* Wl_user  = (const float*)d_in[10];
    const float* bl_user  = (const float*)d_in[11];
    const float* Wl_item  = (const float*)d_in[12];
    const float* bl_item  = (const float*)d_in[13];
    const int*   src_ui   = (const int*)d_in[14];
    const int*   dst_ui   = (const int*)d_in[15];
    const int*   src_iu   = (const int*)d_in[16];
    const int*   dst_iu   = (const int*)d_in[17];

    const int n_user = in_sizes[0] / D_IN;
    const int n_item = in_sizes[1] / D_IN;
    const int E      = in_sizes[14];

    float* H_user = (float*)d_out;
    float* H_item = (float*)d_out + (size_t)n_user * D_OUT;

    void* p_xwu = nullptr; void* p_xwi = nullptr;
    cudaGetSymbolAddress(&p_xwu, g_xwu);
    cudaGetSymbolAddress(&p_xwi, g_xwi);
    float* xwu = (float*)p_xwu;
    float* xwi = (float*)p_xwi;

    cudaFuncSetAttribute(node_kernel,
                         cudaFuncAttributeMaxDynamicSharedMemorySize,
                         NODE_SMEM_BYTES);

    dim3 gu((n_user + NODE_ROWS - 1) / NODE_ROWS, 2);
    dim3 gi((n_item + NODE_ROWS - 1) / NODE_ROWS, 2);

    // users: Y1 = X@W_src_ui + b_ui (scratch), Y2 = X@Wl_user + bl_user (out)
    node_kernel<<<gu, NODE_THREADS, NODE_SMEM_BYTES>>>(
        X_user, W_src_ui, b_ui, xwu, Wl_user, bl_user, H_user, n_user);

    node_kernel<<<gi, NODE_THREADS, NODE_SMEM_BYTES>>>(
        X_item, W_src_iu, b_iu, xwi, Wl_item, bl_item, H_item, n_item);

    const int rel_grid = 148 * 3;
    rel_kernel<<<rel_grid, REL_THREADS>>>(xwu, Xe_ui, src_ui, dst_ui, W_edge_ui, H_item, E);
    rel_kernel<<<rel_grid, REL_THREADS>>>(xwi, Xe_iu, src_iu, dst_iu, W_edge_iu, H_user, E);
}